// round 17
// baseline (speedup 1.0000x reference)
#include <cuda_runtime.h>
#include <cuda_fp16.h>
#include <cstdint>

#define NB 8
#define TT 2048
#define CC 1024
#define MM (NB*TT)          // 16384

// ---------------- scratch (static __device__; no allocation) ----------------
__device__ __align__(256) float  g_kvr[(size_t)MM*3*CC];   // [m][k|v|r] fp32
__device__ __align__(256) __half g_kh[(size_t)MM*CC];
__device__ __align__(256) __half g_vh[(size_t)MM*CC];
__device__ __align__(256) __half g_rh[(size_t)MM*CC];
__device__ __align__(256) __half g_y [(size_t)MM*CC];

__device__ __align__(256) __half g_Wkvr[(size_t)3*CC*CC];  // [3072][1024]
__device__ __align__(256) __half g_Woh[CC*CC];
// flags[0..127]   : kvr rowblock (128 rows) completion, counts to 24 tiles
// flags[256..383] : y rowblock completion, counts to 4 scan blocks
__device__ int g_flags[512];

// ---------------- PTX helpers (architecture-stable, sm_80-era) ----------------
__device__ __forceinline__ uint32_t smem_u32(const void* p) {
    uint32_t a;
    asm("{ .reg .u64 t; cvta.to.shared.u64 t, %1; cvt.u32.u64 %0, t; }" : "=r"(a) : "l"(p));
    return a;
}
__device__ __forceinline__ void cp16(uint32_t saddr, const void* g) {
    asm volatile("cp.async.cg.shared.global [%0], [%1], 16;" :: "r"(saddr), "l"(g));
}
__device__ __forceinline__ void cp_commit() {
    asm volatile("cp.async.commit_group;" ::: "memory");
}
template<int N> __device__ __forceinline__ void cp_wait() {
    asm volatile("cp.async.wait_group %0;" :: "n"(N) : "memory");
}
__device__ __forceinline__ void ldsm4(uint32_t* r, uint32_t addr) {
    asm volatile("ldmatrix.sync.aligned.m8n8.x4.shared.b16 {%0,%1,%2,%3}, [%4];"
                 : "=r"(r[0]), "=r"(r[1]), "=r"(r[2]), "=r"(r[3]) : "r"(addr));
}
__device__ __forceinline__ void mma_f16(float* c, const uint32_t* a, uint32_t b0, uint32_t b1) {
    asm volatile(
        "mma.sync.aligned.m16n8k16.row.col.f32.f16.f16.f32 "
        "{%0,%1,%2,%3}, {%4,%5,%6,%7}, {%8,%9}, {%0,%1,%2,%3};"
        : "+f"(c[0]), "+f"(c[1]), "+f"(c[2]), "+f"(c[3])
        : "r"(a[0]), "r"(a[1]), "r"(a[2]), "r"(a[3]), "r"(b0), "r"(b1));
}

// ---------------- tiling ----------------
#define BM 128
#define BN 128
#define BK 64
#define A_SZ (BM*128)                  // 16 KB
#define B_SZ (BN*128)                  // 16 KB
#define STAGE (A_SZ + B_SZ)            // 32 KB
#define NSTAGE 3
#define GEMM_SMEM (NSTAGE*STAGE)       // 96 KB -> 2 CTAs/SM

#define NSCAN 32
#define KVR_TX 24
#define OUT_TX 8
#define NRB (MM/BM)                    // 128 rowblocks
#define TILES_PER_RB (KVR_TX + OUT_TX) // 32

// ---------------- GEMM role (device) ----------------
// 8 warps: 4(M) x 2(N), warp tile 32x64. Single-barrier 3-stage pipeline.
__device__ __forceinline__ void gemm_role(
    int bx, int by,
    const __half* __restrict__ A, const __half* __restrict__ W,
    float* __restrict__ Cout, int ldc,
    int wait_y, int set_kvr, char* smem, int tid)
{
    const uint32_t sbase = smem_u32(smem);
    const int wid = tid >> 5, lid = tid & 31;
    const int warp_m = wid & 3, warp_n = wid >> 2;
    const int M0 = by * BM, N0 = bx * BN;

    if (wait_y) {     // out-GEMM: wait for scan to finish this 128-row chunk of y
        if (tid == 0) {
            while (atomicAdd(&g_flags[256 + by], 0) < 4) __nanosleep(256);
        }
        __syncthreads();
        __threadfence();
    }

    float acc[2][8][4];
    #pragma unroll
    for (int i = 0; i < 2; i++)
        #pragma unroll
        for (int j = 0; j < 8; j++)
            #pragma unroll
            for (int q = 0; q < 4; q++) acc[i][j][q] = 0.f;

    auto load_stage = [&](int s) {
        const uint32_t base = sbase + (s % NSTAGE) * STAGE;
        const int k0 = s * BK;
        #pragma unroll
        for (int i = 0; i < 4; i++) {                 // A+B: 1024 chunks each
            const int c = tid + i * 256;
            const int r = c >> 3, j = c & 7;
            uint32_t off = r * 128 + j * 16;
            uint32_t sw = off ^ ((off >> 3) & 0x70);
            cp16(base + sw,        (const char*)A + ((size_t)(M0 + r) * CC + k0) * 2 + j * 16);
            cp16(base + A_SZ + sw, (const char*)W + ((size_t)(N0 + r) * CC + k0) * 2 + j * 16);
        }
        cp_commit();
    };

    load_stage(0); load_stage(1);

    const int nk = CC / BK;   // 16
    for (int s = 0; s < nk; s++) {
        if (s < nk - 1) cp_wait<1>();
        else            cp_wait<0>();
        __syncthreads();
        if (s + 2 < nk) load_stage(s + 2);

        const uint32_t bA = sbase + (s % NSTAGE) * STAGE;
        const uint32_t bB = bA + A_SZ;

        #pragma unroll
        for (int st = 0; st < 4; st++) {              // 4 x k16
            const int cb = st * 32 + ((lid >> 4) * 16);
            uint32_t ah[2][4], bh[4][4];
            #pragma unroll
            for (int i = 0; i < 2; i++) {
                const int r = warp_m * 32 + i * 16 + (lid & 15);
                uint32_t off = r * 128 + cb;
                uint32_t sw = off ^ ((off >> 3) & 0x70);
                ldsm4(ah[i], bA + sw);
            }
            #pragma unroll
            for (int q = 0; q < 4; q++) {
                const int r = warp_n * 64 + q * 16 + (lid & 15);
                uint32_t off = r * 128 + cb;
                uint32_t sw = off ^ ((off >> 3) & 0x70);
                ldsm4(bh[q], bB + sw);
            }
            #pragma unroll
            for (int i = 0; i < 2; i++)
                #pragma unroll
                for (int j = 0; j < 8; j++) {
                    const int q = j >> 1, h = j & 1;
                    mma_f16(acc[i][j], ah[i], bh[q][h], bh[q][2 + h]);
                }
        }
    }

    // epilogue
    #pragma unroll
    for (int i = 0; i < 2; i++) {
        const int row = M0 + warp_m * 32 + i * 16 + (lid >> 2);
        #pragma unroll
        for (int j = 0; j < 8; j++) {
            const int col = N0 + warp_n * 64 + j * 8 + (lid & 3) * 2;
            *(float2*)&Cout[(size_t)row * ldc + col]       = make_float2(acc[i][j][0], acc[i][j][1]);
            *(float2*)&Cout[(size_t)(row + 8) * ldc + col] = make_float2(acc[i][j][2], acc[i][j][3]);
        }
    }

    if (set_kvr) {
        __threadfence();
        __syncthreads();
        if (tid == 0) atomicAdd(&g_flags[by], 1);
    }
}

// ---------------- scan role (device): prefetch + reduced-MUFU math ----------------
// tau = max(ukt,e) => one of e1,e2 is exactly 1: compute exp(-|d|) + selects.
// Sigmoid fused into the wkv divide: one divide total.
#define PD 8
__device__ __forceinline__ void scan_role(
    int bi, int tid,
    const float* __restrict__ td, const float* __restrict__ tf,
    const float* __restrict__ state)
{
    const int ch = bi * 256 + tid;          // 0..8191; one block = quarter batch
    const int n = ch >> 10;
    const int c = ch & (CC - 1);

    const float u = tf[c];
    const float w = __expf(td[c]);

    const float* st = state + (size_t)n * 3 * CC;
    float a = st[c];
    float b = st[CC + c];
    float e = st[2 * CC + c];

    const size_t row0 = (size_t)n * TT;
    float kq[PD], vq[PD], rq[PD];

    for (int t0 = 0; t0 < TT; t0 += BM) {             // 128-row chunks
        const int rb = n * (TT / BM) + (t0 / BM);     // global 128-row block index
        if (tid == 0) {
            while (atomicAdd(&g_flags[rb], 0) < KVR_TX) __nanosleep(128);
        }
        __syncthreads();
        __threadfence();

        const size_t rbase = row0 + t0;
        #pragma unroll
        for (int d = 0; d < PD; d++) {
            const size_t b3 = (rbase + d) * (3 * CC);
            kq[d] = __ldcg(&g_kvr[b3 + c]);
            vq[d] = __ldcg(&g_kvr[b3 + CC + c]);
            rq[d] = __ldcg(&g_kvr[b3 + 2 * CC + c]);
        }

        #pragma unroll 8
        for (int t = 0; t < BM; t++) {
            const float kt = kq[t & (PD-1)];
            const float vt = vq[t & (PD-1)];
            const float rr = rq[t & (PD-1)];
            if (t < BM - PD) {
                const size_t b3 = (rbase + t + PD) * (3 * CC);
                kq[t & (PD-1)] = __ldcg(&g_kvr[b3 + c]);
                vq[t & (PD-1)] = __ldcg(&g_kvr[b3 + CC + c]);
                rq[t & (PD-1)] = __ldcg(&g_kvr[b3 + 2 * CC + c]);
            }

            // wkv_t = (e1*a + e2*vt) / (e1*b + e2), tau = max(u+kt, e)
            const float d1 = e - (u + kt);            // e - ukt
            const float ed = __expf(-fabsf(d1));
            const float e1 = (d1 >= 0.f) ? 1.f : ed;
            const float e2 = (d1 >= 0.f) ? ed : 1.f;
            const float num = e1 * a + e2 * vt;
            const float den = e1 * b + e2;

            // y = wkv * sigmoid(rr) = num / (den * (1 + exp(-rr)))
            const float es = __expf(-rr);
            const float y  = __fdividef(num, den * (1.f + es));
            g_y[(rbase + t) * CC + c] = __float2half_rn(y);

            // state update: en = max(e - w, kt)
            const float we = e - w;
            const float d2 = we - kt;
            const float edn = __expf(-fabsf(d2));
            const float e1n = (d2 >= 0.f) ? 1.f : edn;
            const float e2n = (d2 >= 0.f) ? edn : 1.f;
            a = e1n * a + e2n * vt;
            b = e1n * b + e2n;
            e = fmaxf(we, kt);
        }

        __threadfence();
        __syncthreads();
        if (tid == 0) atomicAdd(&g_flags[256 + rb], 1);   // 4 scan blocks per batch
    }
}

// ---------------- mega kernel: 32 scan | interleaved (24 kvr + 8 out) per rowblock ----------------
__global__ void __launch_bounds__(256, 2)
mega(const __half* __restrict__ A0, const __half* __restrict__ A1,
     const __half* __restrict__ A2, const __half* __restrict__ Wkvr,
     float* __restrict__ Ckvr,
     const __half* __restrict__ Ay, const __half* __restrict__ Wo,
     float* __restrict__ Cout,
     const float* __restrict__ td, const float* __restrict__ tf,
     const float* __restrict__ state)
{
    extern __shared__ char smem[];
    const int tid = threadIdx.x;
    const int bi = blockIdx.x;

    if (bi < NSCAN) {
        scan_role(bi, tid, td, tf, state);
        return;
    }
    const int t = bi - NSCAN;
    const int rb = t / TILES_PER_RB;          // rowblock (by)
    const int slot = t % TILES_PER_RB;
    if (slot < KVR_TX) {
        const int bx = slot;
        const int sel = bx >> 3;              // bx/8: 0..2 selects k/v/r mixed input
        const __half* A = (sel == 0) ? A0 : (sel == 1) ? A1 : A2;
        gemm_role(bx, rb, A, Wkvr, Ckvr, KVR_TX * BN, 0, 1, smem, tid);
    } else {
        const int bx = slot - KVR_TX;
        gemm_role(bx, rb, Ay, Wo, Cout, OUT_TX * BN, 1, 0, smem, tid);
    }
}

// ---------------- merged weight convert (also zeroes flags) ----------------
__global__ void __launch_bounds__(256)
conv_all(const float* __restrict__ Wk, const float* __restrict__ Wv,
         const float* __restrict__ Wr, const float* __restrict__ Wo)
{
    if (blockIdx.x < 2) g_flags[blockIdx.x * 256 + threadIdx.x] = 0;   // 512 flags

    const size_t gid = (size_t)blockIdx.x * blockDim.x + threadIdx.x;  // 1M threads
    const int mat = (int)(gid >> 18);                // 256K threads per matrix
    const size_t off = (gid & 0x3FFFF) * 4;
    const float* src = (mat == 0) ? Wk : (mat == 1) ? Wv : (mat == 2) ? Wr : Wo;
    __half* dst = (mat < 3) ? (g_Wkvr + (size_t)mat * CC * CC) : g_Woh;

    const float4 w = *(const float4*)&src[off];
    struct h4 { __half v[4]; };
    h4 o;
    o.v[0] = __float2half_rn(w.x);
    o.v[1] = __float2half_rn(w.y);
    o.v[2] = __float2half_rn(w.z);
    o.v[3] = __float2half_rn(w.w);
    *(h4*)&dst[off] = o;
}

// ---------------- mix + fp16 convert ----------------
__global__ void __launch_bounds__(256)
mix_h(const float* __restrict__ x, const float* __restrict__ lastx,
      const float* __restrict__ tmk, const float* __restrict__ tmv,
      const float* __restrict__ tmr)
{
    const int i = blockIdx.x * blockDim.x + threadIdx.x;   // 0 .. MM*CC/4-1
    const int m = i >> 8;
    const int c4 = (i & 255) * 4;
    const int n = m >> 11;
    const size_t e = (size_t)m * CC + c4;

    const float4 xv = *(const float4*)&x[e];
    const float4 l4 = *(const float4*)&lastx[(size_t)n * CC + c4];
    const float4 tk = *(const float4*)&tmk[c4];
    const float4 tv = *(const float4*)&tmv[c4];
    const float4 tr = *(const float4*)&tmr[c4];

    const float xs[4] = {xv.x, xv.y, xv.z, xv.w};
    const float ls[4] = {l4.x, l4.y, l4.z, l4.w};
    const float tks[4] = {tk.x, tk.y, tk.z, tk.w};
    const float tvs[4] = {tv.x, tv.y, tv.z, tv.w};
    const float trs[4] = {tr.x, tr.y, tr.z, tr.w};

    struct h4 { __half v[4]; };
    h4 kh, vh, rh;
    #pragma unroll
    for (int q = 0; q < 4; q++) {
        kh.v[q] = __float2half_rn(xs[q] * tks[q] + ls[q] * (1.f - tks[q]));
        vh.v[q] = __float2half_rn(xs[q] * tvs[q] + ls[q] * (1.f - tvs[q]));
        rh.v[q] = __float2half_rn(xs[q] * trs[q] + ls[q] * (1.f - trs[q]));
    }
    *(h4*)&g_kh[e] = kh;
    *(h4*)&g_vh[e] = vh;
    *(h4*)&g_rh[e] = rh;
}

// ---------------- launch ----------------
extern "C" void kernel_launch(void* const* d_in, const int* in_sizes, int n_in,
                              void* d_out, int out_size)
{
    const float* x     = (const float*)d_in[0];
    const float* Wk    = (const float*)d_in[2];
    const float* Wv    = (const float*)d_in[3];
    const float* Wr    = (const float*)d_in[4];
    const float* Wo    = (const float*)d_in[5];
    const float* tmk   = (const float*)d_in[6];
    const float* tmv   = (const float*)d_in[7];
    const float* tmr   = (const float*)d_in[8];
    const float* td    = (const float*)d_in[9];
    const float* tf    = (const float*)d_in[10];
    const float* lastx = (const float*)d_in[11];
    const float* state = (const float*)d_in[12];
    float* out = (float*)d_out;

    float* kvrp;
    cudaGetSymbolAddress((void**)&kvrp, g_kvr);

    __half *kh, *vh, *rh, *yp;
    cudaGetSymbolAddress((void**)&kh, g_kh);
    cudaGetSymbolAddress((void**)&vh, g_vh);
    cudaGetSymbolAddress((void**)&rh, g_rh);
    cudaGetSymbolAddress((void**)&yp, g_y);

    __half *wkvr, *woh;
    cudaGetSymbolAddress((void**)&wkvr, g_Wkvr);
    cudaGetSymbolAddress((void**)&woh, g_Woh);

    cudaFuncSetAttribute(mega, cudaFuncAttributeMaxDynamicSharedMemorySize, GEMM_SMEM);

    // merged weight convert + flag zeroing
    conv_all<<<4096, 256>>>(Wk, Wv, Wr, Wo);

    mix_h<<<(MM * CC / 4 + 255) / 256, 256>>>(x, lastx, tmk, tmv, tmr);

    // one mega kernel: 32 scan + 128 rowblocks x (24 kvr + 8 out) tiles
    mega<<<NSCAN + NRB * TILES_PER_RB, 256, GEMM_SMEM>>>(
        kh, vh, rh, wkvr, kvrp, yp, woh, out, td, tf, state);
}